// round 2
// baseline (speedup 1.0000x reference)
#include <cuda_runtime.h>

#define BB 256
#define NN 2048
#define DD 128
#define NTR 2047                    // NN-1 non-anchor nodes per batch
#define TOTAL_ROWS (BB*NTR)         // 524032
#define TILE_R 64
#define NUM_TILES (TOTAL_ROWS/TILE_R)  // 8188 (exact)
#define SMEM_MAIN ((16384 + 2*TILE_R*32)*4 + TILE_R*2*4)

// ---- device scratch (no allocations allowed) ----
__device__ float g_acc[BB*DD];        // segment sums of relu(h)
__device__ int   g_counts[BB];        // rows per segment
__device__ int   g_cursor[BB*8];      // scatter cursors (strided to spread LTS)
__device__ int   g_perm[TOTAL_ROWS];  // emb row index g, sorted by bidx
__device__ float g_T[BB*DD];          // W1a @ target_b + b1
__device__ float g_W1bT[DD*DD];       // W1b transposed: [k][d]

// ---- packed f32x2 helpers (B300: doubles fp32 FMA throughput) ----
static __device__ __forceinline__ unsigned long long pack2(float x, float y){
  unsigned long long r; asm("mov.b64 %0, {%1,%2};" : "=l"(r) : "f"(x), "f"(y)); return r;
}
static __device__ __forceinline__ float2 unpack2(unsigned long long v){
  float2 r; asm("mov.b64 {%0,%1}, %2;" : "=f"(r.x), "=f"(r.y) : "l"(v)); return r;
}
static __device__ __forceinline__ void fma2(unsigned long long &d, unsigned long long a, unsigned long long b){
  asm("fma.rn.f32x2 %0, %1, %2, %0;" : "+l"(d) : "l"(a), "l"(b));
}

__global__ void k_zero(){
  int i = blockIdx.x*blockDim.x + threadIdx.x;
  if (i < BB*DD) g_acc[i] = 0.f;
  if (i < BB) g_counts[i] = 0;
}

__global__ void k_hist(const int* __restrict__ bidx){
  __shared__ int h[BB];
  for (int i=threadIdx.x;i<BB;i+=blockDim.x) h[i]=0;
  __syncthreads();
  int stride = blockDim.x*gridDim.x;
  for (int g = blockIdx.x*blockDim.x + threadIdx.x; g < BB*NN; g += stride)
    if (g & (NN-1)) atomicAdd(&h[bidx[g]], 1);
  __syncthreads();
  for (int i=threadIdx.x;i<BB;i+=blockDim.x){ int c=h[i]; if (c) atomicAdd(&g_counts[i], c); }
}

__global__ void k_scan(){
  __shared__ int s[BB];
  int t = threadIdx.x;
  int v0 = g_counts[t];
  s[t] = v0;
  __syncthreads();
  for (int d=1; d<BB; d<<=1){
    int v = (t>=d) ? s[t-d] : 0;
    __syncthreads();
    s[t] += v;
    __syncthreads();
  }
  g_cursor[t*8] = s[t] - v0;   // exclusive prefix
}

__global__ void k_scatter(const int* __restrict__ bidx){
  int stride = blockDim.x*gridDim.x;
  for (int g = blockIdx.x*blockDim.x + threadIdx.x; g < BB*NN; g += stride)
    if (g & (NN-1)){
      int v = bidx[g];
      int pos = atomicAdd(&g_cursor[v*8], 1);
      g_perm[pos] = g;
    }
}

// T[b][d] = sum_k W1[d][k] * embs[b*NN + 0][k] + b1[d]   (k < 128: target half)
__global__ void k_prepT(const float* __restrict__ embs, const float* __restrict__ W1,
                        const float* __restrict__ b1){
  __shared__ float tg[DD];
  int b = blockIdx.x, t = threadIdx.x;
  tg[t] = embs[(size_t)b*NN*DD + t];
  __syncthreads();
  float s = b1[t];
  const float* w = W1 + (size_t)t*2*DD;
  #pragma unroll 8
  for (int k=0;k<DD;k++) s += w[k]*tg[k];
  g_T[b*DD + t] = s;
}

// W1bT[k][d] = W1[d][128+k]
__global__ void k_prepW(const float* __restrict__ W1){
  int d = blockIdx.x, k = threadIdx.x;
  g_W1bT[k*DD + d] = W1[(size_t)d*2*DD + DD + k];
}

// Main: H-tile GEMM (64 rows x 128 cols, K=128) + relu + run-length segment reduce
__global__ void __launch_bounds__(256,2) k_main(const float* __restrict__ embs,
                                                const int* __restrict__ bidx){
  extern __shared__ float smem[];
  float* Ws = smem;                 // 128x128 = 16384 floats, [k][d]
  float* Es = smem + 16384;         // double buffer: 2 x (64 rows x 32 k)
  int* sg   = (int*)(smem + 16384 + 2*TILE_R*32);
  int* sseg = sg + TILE_R;

  int tid = threadIdx.x;
  int tc = tid & 15;        // 16 col-groups of 8 columns
  int tr = tid >> 4;        // 16 row-groups of 4 rows
  int tile = blockIdx.x;

  // load W1bT into smem (coalesced, conflict-free)
  {
    const float4* src = (const float4*)g_W1bT;
    float4* dst = (float4*)Ws;
    #pragma unroll
    for (int i=0;i<16;i++) dst[tid + i*256] = src[tid + i*256];
  }
  if (tid < TILE_R){
    int g = g_perm[tile*TILE_R + tid];
    sg[tid] = g;
    sseg[tid] = bidx[g];
  }
  __syncthreads();

  unsigned long long acc[4][4];
  #pragma unroll
  for (int r=0;r<4;r++){
    #pragma unroll
    for (int c=0;c<4;c++) acc[r][c] = 0ULL;
  }

  // E chunk staging: 512 float4 per 32-k chunk, 2 per thread
  int r0  = tid >> 3;           // rows 0..31 (second load covers +32)
  int kq0 = tid & 7;
  const float* e0 = embs + (size_t)sg[r0]*DD      + kq0*4;
  const float* e1 = embs + (size_t)sg[r0+32]*DD   + kq0*4;
  float* es0 = Es + r0*32 + kq0*4;
  float* es1 = Es + (r0+32)*32 + kq0*4;

  float4 pre0 = *(const float4*)(e0);
  float4 pre1 = *(const float4*)(e1);
  *(float4*)es0 = pre0;
  *(float4*)es1 = pre1;
  pre0 = *(const float4*)(e0 + 32);
  pre1 = *(const float4*)(e1 + 32);
  __syncthreads();

  for (int kb=0; kb<4; kb++){
    const float* eb = Es + (kb&1)*(TILE_R*32);
    const float* wb = Ws + kb*32*DD;
    #pragma unroll
    for (int kk4=0; kk4<8; kk4++){
      float4 a4[4];
      #pragma unroll
      for (int rr=0; rr<4; rr++)
        a4[rr] = *(const float4*)(eb + (tr*4+rr)*32 + kk4*4);
      #pragma unroll
      for (int j=0;j<4;j++){
        const float* wrow = wb + (kk4*4+j)*DD + tc*8;
        ulonglong2 bp0 = *(const ulonglong2*)(wrow);
        ulonglong2 bp1 = *(const ulonglong2*)(wrow + 4);
        #pragma unroll
        for (int rr=0;rr<4;rr++){
          float av = ((const float*)&a4[rr])[j];
          unsigned long long aa = pack2(av, av);
          fma2(acc[rr][0], aa, bp0.x);
          fma2(acc[rr][1], aa, bp0.y);
          fma2(acc[rr][2], aa, bp1.x);
          fma2(acc[rr][3], aa, bp1.y);
        }
      }
    }
    if (kb < 3){
      __syncthreads();
      float* d0 = Es + ((kb+1)&1)*(TILE_R*32) + r0*32 + kq0*4;
      float* d1 = d0 + 32*32;
      *(float4*)d0 = pre0;
      *(float4*)d1 = pre1;
      if (kb < 2){
        pre0 = *(const float4*)(e0 + (kb+2)*32);
        pre1 = *(const float4*)(e1 + (kb+2)*32);
      }
      __syncthreads();
    }
  }

  // epilogue: +T, relu, run-length reduce over (sorted) rows, RED flush
  int prevseg = -1;
  float sum[8];
  #pragma unroll
  for (int rr=0; rr<4; rr++){
    int lr = tr*4 + rr;
    int g = sg[lr];
    int seg = sseg[lr];
    int b = g >> 11;                       // NN = 2048
    const float* Trow = g_T + b*DD + tc*8;
    float v[8];
    #pragma unroll
    for (int cp=0; cp<4; cp++){
      float2 t2 = *(const float2*)(Trow + 2*cp);
      float2 hv = unpack2(acc[rr][cp]);
      v[2*cp]   = fmaxf(hv.x + t2.x, 0.f);
      v[2*cp+1] = fmaxf(hv.y + t2.y, 0.f);
    }
    if (seg == prevseg){
      #pragma unroll
      for (int c=0;c<8;c++) sum[c] += v[c];
    } else {
      if (prevseg >= 0){
        float* dst = g_acc + prevseg*DD + tc*8;
        #pragma unroll
        for (int c=0;c<8;c++) atomicAdd(dst + c, sum[c]);
      }
      #pragma unroll
      for (int c=0;c<8;c++) sum[c] = v[c];
      prevseg = seg;
    }
  }
  {
    float* dst = g_acc + prevseg*DD + tc*8;
    #pragma unroll
    for (int c=0;c<8;c++) atomicAdd(dst + c, sum[c]);
  }
}

// out[s][d] = sum_j W2[d][j] * acc[s][j] + b2[d]*count_s
__global__ void k_final(const float* __restrict__ W2, const float* __restrict__ b2,
                        float* __restrict__ out){
  __shared__ float arow[DD];
  __shared__ int cnt;
  int s = blockIdx.x, d = threadIdx.x;
  arow[d] = g_acc[s*DD + d];
  if (d == 0) cnt = g_counts[s];
  __syncthreads();
  float r = 0.f;
  const float* w = W2 + (size_t)d*DD;
  #pragma unroll 8
  for (int j=0;j<DD;j++) r += w[j]*arow[j];
  out[s*DD + d] = r + b2[d]*(float)cnt;
}

extern "C" void kernel_launch(void* const* d_in, const int* in_sizes, int n_in,
                              void* d_out, int out_size){
  const float* embs = (const float*)d_in[0];
  const float* W1   = (const float*)d_in[1];
  const float* b1   = (const float*)d_in[2];
  const float* W2   = (const float*)d_in[3];
  const float* b2   = (const float*)d_in[4];
  const int*   bidx = (const int*)d_in[5];
  float* out = (float*)d_out;

  cudaFuncSetAttribute(k_main, cudaFuncAttributeMaxDynamicSharedMemorySize, SMEM_MAIN);

  k_zero   <<<(BB*DD + 255)/256, 256>>>();
  k_hist   <<<256, 256>>>(bidx);
  k_scan   <<<1, BB>>>();
  k_scatter<<<256, 256>>>(bidx);
  k_prepT  <<<BB, DD>>>(embs, W1, b1);
  k_prepW  <<<DD, DD>>>(W1);
  k_main   <<<NUM_TILES, 256, SMEM_MAIN>>>(embs, bidx);
  k_final  <<<BB, DD>>>(W2, b2, out);
}

// round 4
// speedup vs baseline: 5.0911x; 5.0911x over previous
#include <cuda_runtime.h>
#include <cuda_fp16.h>
#include <cstdint>

#define BB 256
#define NN 2048
#define DD 128
#define RPB 2048                  // padded rows per batch (2047 real + 1 dummy)
#define TILE_R 64
#define TILES (BB*32)             // 8192 tiles of 64 rows
#define GRID_MAIN 444             // 3 persistent CTAs per SM (148 SMs)
#define SMEM_MAIN 66816           // W 32768 + max(E 16384, D 33792) + segs 256

// ---------------- device scratch ----------------
__device__ float g_acc[BB*DD];
__device__ int   g_counts[BB];
__device__ int   g_hist[BB*BB];
__device__ int   g_cursor[BB*BB];
__device__ int   g_perm[BB*RPB];
__device__ int   g_segs[BB*RPB];
__device__ float g_T[BB*DD];

// ---------------- helpers ----------------
static __device__ __forceinline__ uint32_t smem_u32(const void* p){
  uint32_t a;
  asm("{ .reg .u64 t; cvta.to.shared.u64 t, %1; cvt.u32.u64 %0, t; }" : "=r"(a) : "l"(p));
  return a;
}
static __device__ __forceinline__ uint32_t h2u(__half2 h){
  union { __half2 h; uint32_t u; } c; c.h = h; return c.u;
}
static __device__ __forceinline__ void ldsm4(uint32_t &r0, uint32_t &r1, uint32_t &r2, uint32_t &r3, uint32_t a){
  asm volatile("ldmatrix.sync.aligned.m8n8.x4.shared.b16 {%0,%1,%2,%3}, [%4];"
    : "=r"(r0), "=r"(r1), "=r"(r2), "=r"(r3) : "r"(a));
}
static __device__ __forceinline__ void mma16816(float* c, uint32_t a0, uint32_t a1, uint32_t a2, uint32_t a3,
                                                uint32_t b0, uint32_t b1){
  asm volatile("mma.sync.aligned.m16n8k16.row.col.f32.f16.f16.f32 "
    "{%0,%1,%2,%3}, {%4,%5,%6,%7}, {%8,%9}, {%0,%1,%2,%3};"
    : "+f"(c[0]), "+f"(c[1]), "+f"(c[2]), "+f"(c[3])
    : "r"(a0), "r"(a1), "r"(a2), "r"(a3), "r"(b0), "r"(b1));
}

// ---------------- prep kernels ----------------
__global__ void k_zero(){
  int i = blockIdx.x*blockDim.x + threadIdx.x;
  if (i < BB*DD) g_acc[i] = 0.f;
  if (i < BB) g_counts[i] = 0;
}

__global__ void k_hist(const int* __restrict__ bidx){
  __shared__ int h[BB];
  int b = blockIdx.x, t = threadIdx.x;
  h[t] = 0; __syncthreads();
  for (int i = t; i < NN-1; i += blockDim.x)
    atomicAdd(&h[bidx[b*NN + 1 + i]], 1);
  __syncthreads();
  g_hist[b*BB + t] = h[t];
}

__global__ void k_scan(){
  __shared__ int s[BB];
  int b = blockIdx.x, t = threadIdx.x;
  int v = g_hist[b*BB + t];
  atomicAdd(&g_counts[t], v);
  s[t] = v; __syncthreads();
  for (int d = 1; d < BB; d <<= 1){
    int x = (t >= d) ? s[t-d] : 0;
    __syncthreads();
    s[t] += x;
    __syncthreads();
  }
  g_cursor[b*BB + t] = s[t] - v;
}

__global__ void k_scatter(const int* __restrict__ bidx){
  __shared__ int cur[BB];
  int b = blockIdx.x, t = threadIdx.x;
  cur[t] = g_cursor[b*BB + t];
  __syncthreads();
  for (int i = t; i < NN-1; i += blockDim.x){
    int g = b*NN + 1 + i;
    int s = bidx[g];
    int pos = atomicAdd(&cur[s], 1);
    g_perm[b*RPB + pos] = g;
    g_segs[b*RPB + pos] = s;
  }
  if (t == 0){ g_perm[b*RPB + NN-1] = b*NN + 1; g_segs[b*RPB + NN-1] = -1; }
}

__global__ void k_prepT(const float* __restrict__ embs, const float* __restrict__ W1,
                        const float* __restrict__ b1){
  __shared__ float tg[DD];
  int b = blockIdx.x, t = threadIdx.x;
  tg[t] = embs[(size_t)b*NN*DD + t];
  __syncthreads();
  float s = b1[t];
  const float* w = W1 + (size_t)t*2*DD;
  #pragma unroll 8
  for (int k = 0; k < DD; k++) s += w[k]*tg[k];
  g_T[b*DD + t] = s;
}

// ---------------- main persistent HMMA kernel ----------------
// SMEM: Wh fp16 [128 rows x 256B, XOR-swizzled] at 0
//       Eh fp16 [64 rows x 256B, XOR-swizzled]  at 32768  (overlaid by D fp32 [64][132])
//       segs [64 int] at 66560
__global__ void __launch_bounds__(128, 3) k_main(const float* __restrict__ embs,
                                                 const float* __restrict__ W1){
  extern __shared__ char sm[];
  float* Dm = (float*)(sm + 32768);
  int* segs = (int*)(sm + 66560);
  uint32_t sbase = smem_u32(sm);
  const uint32_t Wb = sbase, Eb = sbase + 32768;

  int tid = threadIdx.x;
  int lane = tid & 31, w = tid >> 5;

  // ---- convert W1b -> smem fp16 once (row d = tid, 128 k-values) ----
  {
    const float4* wr = (const float4*)(W1 + (size_t)tid*2*DD + DD);
    uint32_t sw = (uint32_t)(tid & 7) << 4;
    char* dst = sm + tid*256;
    #pragma unroll
    for (int i = 0; i < 16; i++){
      float4 v0 = wr[2*i], v1 = wr[2*i+1];
      uint4 q;
      q.x = h2u(__floats2half2_rn(v0.x, v0.y));
      q.y = h2u(__floats2half2_rn(v0.z, v0.w));
      q.z = h2u(__floats2half2_rn(v1.x, v1.y));
      q.w = h2u(__floats2half2_rn(v1.z, v1.w));
      *(uint4*)(dst + (((uint32_t)(i*16)) ^ sw)) = q;
    }
  }

  // ldmatrix lane-dependent bases
  const uint32_t ln15 = lane & 15;
  const uint32_t sxor = (uint32_t)(lane & 7) << 4;
  const uint32_t kbl  = (uint32_t)(lane >> 4) << 4;
  const uint32_t baseA = Eb + (w*16 + ln15)*256;
  const uint32_t baseB = Wb + ln15*256;

  // E gather mapping
  const int er = tid >> 1;
  const int eh = tid & 1;
  const uint32_t esw = (uint32_t)(er & 7) << 4;
  char* edst = sm + 32768 + er*256;

  __syncthreads();   // W ready

  for (int tile = blockIdx.x; tile < TILES; tile += GRID_MAIN){
    int btile = tile >> 5;
    int rowbase = btile*RPB + (tile & 31)*TILE_R;

    __syncthreads();   // previous tile's D fully consumed before overwriting E

    // ---- gather 64 emb rows, convert to fp16, swizzled store ----
    {
      int g = g_perm[rowbase + er];
      const float4* src = (const float4*)(embs + (size_t)g*DD + eh*64);
      #pragma unroll
      for (int i = 0; i < 8; i++){
        float4 v0 = src[2*i], v1 = src[2*i+1];
        uint4 q;
        q.x = h2u(__floats2half2_rn(v0.x, v0.y));
        q.y = h2u(__floats2half2_rn(v0.z, v0.w));
        q.z = h2u(__floats2half2_rn(v1.x, v1.y));
        q.w = h2u(__floats2half2_rn(v1.z, v1.w));
        uint32_t c = (uint32_t)(eh*128 + i*16);
        *(uint4*)(edst + (c ^ esw)) = q;
      }
    }
    if (tid < TILE_R) segs[tid] = g_segs[rowbase + tid];
    __syncthreads();

    // ---- MMA: D[r][d], r = warp's 16 rows, d = 0..127 ----
    float acc[16][4];
    #pragma unroll
    for (int i = 0; i < 16; i++){
      acc[i][0] = 0.f; acc[i][1] = 0.f; acc[i][2] = 0.f; acc[i][3] = 0.f;
    }
    #pragma unroll
    for (int k0 = 0; k0 < 8; k0++){
      uint32_t ko = (((uint32_t)k0 << 5) | kbl) ^ sxor;
      uint32_t a0, a1, a2, a3;
      ldsm4(a0, a1, a2, a3, baseA + ko);
      uint32_t bad = baseB + ko;
      #pragma unroll
      for (int np = 0; np < 8; np++){
        uint32_t b0, b1, b2, b3;
        ldsm4(b0, b1, b2, b3, bad);
        bad += 16*256;
        mma16816(acc[2*np],   a0, a1, a2, a3, b0, b2);
        mma16816(acc[2*np+1], a0, a1, a2, a3, b1, b3);
      }
    }
    __syncthreads();   // all E reads done; D may overwrite E region

    // ---- store D to smem (pad-132, conflict-free) ----
    {
      int r0 = w*16 + (lane >> 2);
      int c0 = 2*(lane & 3);
      #pragma unroll
      for (int nt = 0; nt < 16; nt++){
        *(float2*)(Dm + r0*132 + nt*8 + c0)     = make_float2(acc[nt][0], acc[nt][1]);
        *(float2*)(Dm + (r0+8)*132 + nt*8 + c0) = make_float2(acc[nt][2], acc[nt][3]);
      }
    }
    __syncthreads();

    // ---- epilogue: col d = tid; +T, relu, sorted run-length reduce, RED flush ----
    {
      float t_d = g_T[btile*DD + tid];
      int cur = -1; float run = 0.f;
      #pragma unroll 8
      for (int r = 0; r < TILE_R; r++){
        int s = segs[r];
        float v = fmaxf(Dm[r*132 + tid] + t_d, 0.f);
        if (s != cur){
          if (cur >= 0) atomicAdd(&g_acc[cur*DD + tid], run);
          run = 0.f; cur = s;
        }
        if (s >= 0) run += v;
      }
      if (cur >= 0) atomicAdd(&g_acc[cur*DD + tid], run);
    }
  }
}

// ---------------- final small GEMM ----------------
__global__ void k_final(const float* __restrict__ W2, const float* __restrict__ b2,
                        float* __restrict__ out){
  __shared__ float arow[DD];
  __shared__ int cnt;
  int s = blockIdx.x, d = threadIdx.x;
  arow[d] = g_acc[s*DD + d];
  if (d == 0) cnt = g_counts[s];
  __syncthreads();
  float r = 0.f;
  const float* ww = W2 + (size_t)d*DD;
  #pragma unroll 8
  for (int j = 0; j < DD; j++) r += ww[j]*arow[j];
  out[s*DD + d] = r + b2[d]*(float)cnt;
}

// ---------------- launch ----------------
extern "C" void kernel_launch(void* const* d_in, const int* in_sizes, int n_in,
                              void* d_out, int out_size){
  const float* embs = (const float*)d_in[0];
  const float* W1   = (const float*)d_in[1];
  const float* b1   = (const float*)d_in[2];
  const float* W2   = (const float*)d_in[3];
  const float* b2   = (const float*)d_in[4];
  const int*   bidx = (const int*)d_in[5];
  float* out = (float*)d_out;

  cudaFuncSetAttribute(k_main, cudaFuncAttributeMaxDynamicSharedMemorySize, SMEM_MAIN);

  k_zero   <<<(BB*DD + 255)/256, 256>>>();
  k_hist   <<<BB, BB>>>(bidx);
  k_scan   <<<BB, BB>>>();
  k_scatter<<<BB, BB>>>(bidx);
  k_prepT  <<<BB, DD>>>(embs, W1, b1);
  k_main   <<<GRID_MAIN, 128, SMEM_MAIN>>>(embs, W1);
  k_final  <<<BB, DD>>>(W2, b2, out);
}

// round 5
// speedup vs baseline: 5.3740x; 1.0556x over previous
#include <cuda_runtime.h>
#include <cuda_fp16.h>
#include <cstdint>

#define BB 256
#define NN 2048
#define DD 128
#define RPB 2048
#define TILE_R 64
#define TILES (BB*32)             // 8192 tiles
#define GRID_MAIN 296             // 2 persistent CTAs/SM
// smem layout (bytes): W16 [0,32768) | E16/D overlay [32768,66560) | stage32 [66560,99328) | segs [99328,99584)
#define SMEM_MAIN 99584

// ---------------- device scratch ----------------
__device__ float g_acc[BB*DD];
__device__ int   g_hist[BB*BB];
__device__ int   g_perm[BB*RPB];
__device__ int   g_segs[BB*RPB];
__device__ float g_T[BB*DD];

// ---------------- helpers ----------------
static __device__ __forceinline__ uint32_t smem_u32(const void* p){
  uint32_t a;
  asm("{ .reg .u64 t; cvta.to.shared.u64 t, %1; cvt.u32.u64 %0, t; }" : "=r"(a) : "l"(p));
  return a;
}
static __device__ __forceinline__ uint32_t h2u(__half2 h){
  union { __half2 h; uint32_t u; } c; c.h = h; return c.u;
}
static __device__ __forceinline__ void ldsm4(uint32_t &r0, uint32_t &r1, uint32_t &r2, uint32_t &r3, uint32_t a){
  asm volatile("ldmatrix.sync.aligned.m8n8.x4.shared.b16 {%0,%1,%2,%3}, [%4];"
    : "=r"(r0), "=r"(r1), "=r"(r2), "=r"(r3) : "r"(a));
}
static __device__ __forceinline__ void mma16816(float* c, uint32_t a0, uint32_t a1, uint32_t a2, uint32_t a3,
                                                uint32_t b0, uint32_t b1){
  asm volatile("mma.sync.aligned.m16n8k16.row.col.f32.f16.f16.f32 "
    "{%0,%1,%2,%3}, {%4,%5,%6,%7}, {%8,%9}, {%0,%1,%2,%3};"
    : "+f"(c[0]), "+f"(c[1]), "+f"(c[2]), "+f"(c[3])
    : "r"(a0), "r"(a1), "r"(a2), "r"(a3), "r"(b0), "r"(b1));
}
static __device__ __forceinline__ void cp16(uint32_t dst, const float* src){
  asm volatile("cp.async.cg.shared.global [%0], [%1], 16;" :: "r"(dst), "l"(src));
}
#define CP_COMMIT() asm volatile("cp.async.commit_group;" ::: "memory")
#define CP_WAIT0()  asm volatile("cp.async.wait_group 0;" ::: "memory")

// ---------------- fused prep: zero + hist + scan + scatter + prepT ----------------
__global__ void __launch_bounds__(256) k_prep(const int* __restrict__ bidx,
                                              const float* __restrict__ embs,
                                              const float* __restrict__ W1,
                                              const float* __restrict__ b1){
  int b = blockIdx.x, t = threadIdx.x;
  if (b < BB){
    __shared__ int h[BB], sc[BB];
    if (t < DD) g_acc[b*DD + t] = 0.f;
    h[t] = 0;
    __syncthreads();
    for (int i = t; i < NN-1; i += 256)
      atomicAdd(&h[bidx[b*NN + 1 + i]], 1);
    __syncthreads();
    int v = h[t];
    g_hist[b*BB + t] = v;
    sc[t] = v;
    __syncthreads();
    for (int d = 1; d < BB; d <<= 1){
      int x = (t >= d) ? sc[t-d] : 0;
      __syncthreads();
      sc[t] += x;
      __syncthreads();
    }
    h[t] = sc[t] - v;   // cursor = exclusive prefix
    __syncthreads();
    for (int i = t; i < NN-1; i += 256){
      int g = b*NN + 1 + i;
      int s = bidx[g];
      int pos = atomicAdd(&h[s], 1);
      g_perm[b*RPB + pos] = g;
      g_segs[b*RPB + pos] = s;
    }
    if (t == 0){ g_perm[b*RPB + NN-1] = b*NN + 1; g_segs[b*RPB + NN-1] = -1; }
  } else {
    // prepT for batch bb: T[bb][d] = W1[d, 0:128] . target + b1[d]
    int bb = b - BB;
    __shared__ float tg[DD];
    if (t < DD) tg[t] = embs[(size_t)bb*NN*DD + t];
    __syncthreads();
    if (t < DD){
      float s = b1[t];
      const float* w = W1 + (size_t)t*2*DD;
      #pragma unroll 8
      for (int k = 0; k < DD; k++) s += w[k]*tg[k];
      g_T[bb*DD + t] = s;
    }
  }
}

// ---------------- main persistent HMMA kernel (cp.async pipelined) ----------------
__global__ void __launch_bounds__(128, 2) k_main(const float* __restrict__ embs,
                                                 const float* __restrict__ W1){
  extern __shared__ char sm[];
  float* Dm   = (float*)(sm + 32768);
  float4* st4 = (float4*)(sm + 66560);
  int* segs   = (int*)(sm + 99328);
  uint32_t sbase = smem_u32(sm);
  const uint32_t Wb = sbase, Eb = sbase + 32768, Sb = sbase + 66560;

  int tid = threadIdx.x;
  int lane = tid & 31, w = tid >> 5;

  // ---- convert W1b -> smem fp16 once (row d = tid) ----
  {
    const float4* wr = (const float4*)(W1 + (size_t)tid*2*DD + DD);
    uint32_t sw = (uint32_t)(tid & 7) << 4;
    char* dst = sm + tid*256;
    #pragma unroll
    for (int i = 0; i < 16; i++){
      float4 v0 = wr[2*i], v1 = wr[2*i+1];
      uint4 q;
      q.x = h2u(__floats2half2_rn(v0.x, v0.y));
      q.y = h2u(__floats2half2_rn(v0.z, v0.w));
      q.z = h2u(__floats2half2_rn(v1.x, v1.y));
      q.w = h2u(__floats2half2_rn(v1.z, v1.w));
      *(uint4*)(dst + (((uint32_t)(i*16)) ^ sw)) = q;
    }
  }

  // ldmatrix bases
  const uint32_t ln15 = lane & 15;
  const uint32_t sxor = (uint32_t)(lane & 7) << 4;
  const uint32_t kbl  = (uint32_t)(lane >> 4) << 4;
  const uint32_t baseA = Eb + (w*16 + ln15)*256;
  const uint32_t baseB = Wb + ln15*256;

  // gather mapping: thread handles row er, half eh (256B via 16 cp.async)
  const int er = tid >> 1, eh = tid & 1;
  const uint32_t cpdst = Sb + (uint32_t)er*512 + (uint32_t)eh*256;

  // ---- prologue: fetch + convert first tile ----
  int tile = blockIdx.x;
  {
    int rowbase = (tile >> 5)*RPB + (tile & 31)*TILE_R;
    const float* src = embs + (size_t)g_perm[rowbase + er]*DD + eh*64;
    #pragma unroll
    for (int i = 0; i < 16; i++) cp16(cpdst + i*16, src + i*4);
    CP_COMMIT();
    if (tid < TILE_R) segs[tid] = g_segs[rowbase + tid];
    CP_WAIT0();
    __syncthreads();
    #pragma unroll
    for (int i = 0; i < 16; i++){
      int idx = tid + 128*i;
      float4 v = st4[idx];
      uint32_t row = (uint32_t)idx >> 5, c4 = (uint32_t)idx & 31;
      uint2 q;
      q.x = h2u(__floats2half2_rn(v.x, v.y));
      q.y = h2u(__floats2half2_rn(v.z, v.w));
      *(uint2*)(sm + 32768 + row*256 + ((c4*8) ^ ((row & 7) << 4))) = q;
    }
    __syncthreads();
  }

  for (; tile < TILES; tile += GRID_MAIN){
    int nxt = tile + GRID_MAIN;
    int nrowbase = 0;
    if (nxt < TILES){
      nrowbase = (nxt >> 5)*RPB + (nxt & 31)*TILE_R;
      const float* src = embs + (size_t)g_perm[nrowbase + er]*DD + eh*64;
      #pragma unroll
      for (int i = 0; i < 16; i++) cp16(cpdst + i*16, src + i*4);
      CP_COMMIT();
    }

    // ---- MMA: D[r][d] over 64 rows x 128 cols, K=128 ----
    float acc[16][4];
    #pragma unroll
    for (int i = 0; i < 16; i++){
      acc[i][0] = 0.f; acc[i][1] = 0.f; acc[i][2] = 0.f; acc[i][3] = 0.f;
    }
    #pragma unroll
    for (int k0 = 0; k0 < 8; k0++){
      uint32_t ko = (((uint32_t)k0 << 5) | kbl) ^ sxor;
      uint32_t a0, a1, a2, a3;
      ldsm4(a0, a1, a2, a3, baseA + ko);
      uint32_t bad = baseB + ko;
      #pragma unroll
      for (int np = 0; np < 8; np++){
        uint32_t b0, b1, b2, b3;
        ldsm4(b0, b1, b2, b3, bad);
        bad += 16*256;
        mma16816(acc[2*np],   a0, a1, a2, a3, b0, b2);
        mma16816(acc[2*np+1], a0, a1, a2, a3, b1, b3);
      }
    }
    __syncthreads();   // E reads done; D may overwrite

    // ---- store D (pad-132, conflict-free) ----
    {
      int r0 = w*16 + (lane >> 2);
      int c0 = 2*(lane & 3);
      #pragma unroll
      for (int nt = 0; nt < 16; nt++){
        *(float2*)(Dm + r0*132 + nt*8 + c0)     = make_float2(acc[nt][0], acc[nt][1]);
        *(float2*)(Dm + (r0+8)*132 + nt*8 + c0) = make_float2(acc[nt][2], acc[nt][3]);
      }
    }
    __syncthreads();

    // ---- epilogue: col d = tid; +T, relu, sorted run-length reduce ----
    {
      int btile = tile >> 5;
      float t_d = g_T[btile*DD + tid];
      int cur = -1; float run = 0.f;
      #pragma unroll 8
      for (int r = 0; r < TILE_R; r++){
        int s = segs[r];
        float v = fmaxf(Dm[r*132 + tid] + t_d, 0.f);
        if (s != cur){
          if (cur >= 0) atomicAdd(&g_acc[cur*DD + tid], run);
          run = 0.f; cur = s;
        }
        if (s >= 0) run += v;
      }
      if (cur >= 0) atomicAdd(&g_acc[cur*DD + tid], run);
    }

    // ---- drain prefetch, convert next tile into E16 ----
    if (nxt < TILES){
      CP_WAIT0();
      __syncthreads();   // epilogue reads of D/segs done; stage arrived
      if (tid < TILE_R) segs[tid] = g_segs[nrowbase + tid];
      #pragma unroll
      for (int i = 0; i < 16; i++){
        int idx = tid + 128*i;
        float4 v = st4[idx];
        uint32_t row = (uint32_t)idx >> 5, c4 = (uint32_t)idx & 31;
        uint2 q;
        q.x = h2u(__floats2half2_rn(v.x, v.y));
        q.y = h2u(__floats2half2_rn(v.z, v.w));
        *(uint2*)(sm + 32768 + row*256 + ((c4*8) ^ ((row & 7) << 4))) = q;
      }
      __syncthreads();
    }
  }
}

// ---------------- final: out[s] = W2 . acc[s] + b2 * count_s ----------------
__global__ void __launch_bounds__(128) k_final(const float* __restrict__ W2,
                                               const float* __restrict__ b2,
                                               float* __restrict__ out){
  __shared__ float arow[DD];
  __shared__ int red[DD];
  int s = blockIdx.x, d = threadIdx.x;
  arow[d] = g_acc[s*DD + d];
  red[d] = g_hist[d*BB + s] + g_hist[(d + 128)*BB + s];
  __syncthreads();
  #pragma unroll
  for (int o = 64; o > 0; o >>= 1){
    if (d < o) red[d] += red[d + o];
    __syncthreads();
  }
  float r = 0.f;
  const float* ww = W2 + (size_t)d*DD;
  #pragma unroll 8
  for (int j = 0; j < DD; j++) r += ww[j]*arow[j];
  out[s*DD + d] = r + b2[d]*(float)red[0];
}

// ---------------- launch ----------------
extern "C" void kernel_launch(void* const* d_in, const int* in_sizes, int n_in,
                              void* d_out, int out_size){
  const float* embs = (const float*)d_in[0];
  const float* W1   = (const float*)d_in[1];
  const float* b1   = (const float*)d_in[2];
  const float* W2   = (const float*)d_in[3];
  const float* b2   = (const float*)d_in[4];
  const int*   bidx = (const int*)d_in[5];
  float* out = (float*)d_out;

  cudaFuncSetAttribute(k_main, cudaFuncAttributeMaxDynamicSharedMemorySize, SMEM_MAIN);

  k_prep <<<2*BB, 256>>>(bidx, embs, W1, b1);
  k_main <<<GRID_MAIN, 128, SMEM_MAIN>>>(embs, W1);
  k_final<<<BB, DD>>>(W2, b2, out);
}